// round 10
// baseline (speedup 1.0000x reference)
#include <cuda_runtime.h>

#define N_NODES 100000
#define N_EDGES 1600000
#define DIM 128
#define HID 16
#define NCLS 40
#define BN_EPS 1e-5f

typedef unsigned long long ull;

// ---------------- f32x2 packed-math helpers (B300 FFMA2 path) --------------
__device__ __forceinline__ ull pack2(float x, float y) {
    ull r; asm("mov.b64 %0,{%1,%2};" : "=l"(r) : "f"(x), "f"(y)); return r;
}
__device__ __forceinline__ void unpack2(ull v, float& x, float& y) {
    asm("mov.b64 {%0,%1},%2;" : "=f"(x), "=f"(y) : "l"(v));
}
__device__ __forceinline__ ull fma2(ull a, ull b, ull c) {
    ull d; asm("fma.rn.f32x2 %0,%1,%2,%3;" : "=l"(d) : "l"(a), "l"(b), "l"(c)); return d;
}
__device__ __forceinline__ ull add2(ull a, ull b) {
    ull d; asm("add.rn.f32x2 %0,%1,%2;" : "=l"(d) : "l"(a), "l"(b)); return d;
}
__device__ __forceinline__ ull shfl2(ull v, int src) {
    float lo, hi; unpack2(v, lo, hi);
    lo = __shfl_sync(0xffffffffu, lo, src);
    hi = __shfl_sync(0xffffffffu, hi, src);
    return pack2(lo, hi);
}

// ---------------- scratch (static device globals) ---------------------------
__device__ float  g_h1[N_NODES * HID];
__device__ float  g_s1[N_NODES * HID];
__device__ float  g_agg[N_NODES * HID];
__device__ double g_M3[3][HID * HID];
__device__ double g_sum3[3][HID];
__device__ int    g_row_ptr[N_NODES + 1];

#define TB 256
#define NODE_BLK ((N_NODES + TB - 1) / TB)          // 391
#define RP_BLK   ((N_NODES + 1 + TB - 1) / TB)      // 391
#define N_PAIRS  (N_NODES / 2)                      // 50000
#define SPMM_BLK (N_PAIRS / 8)                      // 6250 (warp = pair, exact)
#define STATS_BLK 592                               // strided variant

// ---------------- fused: row_ptr build + stats zero + x@W1 ------------------
__global__ void prolog_kernel(const int* __restrict__ row, const float* __restrict__ x,
                              const float* __restrict__ W, float* __restrict__ y) {
    if (blockIdx.x >= NODE_BLK) {
        int t = threadIdx.x;
        if (blockIdx.x == NODE_BLK) {
            if (t < HID * HID) { g_M3[0][t] = 0.0; g_M3[1][t] = 0.0; g_M3[2][t] = 0.0; }
            if (t < HID) { g_sum3[0][t] = 0.0; g_sum3[1][t] = 0.0; g_sum3[2][t] = 0.0; }
        }
        int i = (blockIdx.x - NODE_BLK) * TB + t;
        if (i > N_NODES) return;
        int lo = 0, hi = N_EDGES;
        while (lo < hi) {
            int mid = (lo + hi) >> 1;
            if (row[mid] < i) lo = mid + 1; else hi = mid;
        }
        g_row_ptr[i] = lo;
        return;
    }
    __shared__ __align__(16) float Ws[DIM * HID];
    for (int i = threadIdx.x; i < DIM * HID; i += TB) Ws[i] = W[i];
    __syncthreads();
    int n = blockIdx.x * TB + threadIdx.x;
    if (n >= N_NODES) return;
    ull acc2[8];
    #pragma unroll
    for (int j = 0; j < 8; j++) acc2[j] = 0ull;
    const float4* xr = reinterpret_cast<const float4*>(x + (size_t)n * DIM);
    #pragma unroll 4
    for (int d4 = 0; d4 < DIM / 4; d4++) {
        float4 xv = xr[d4];
        #pragma unroll
        for (int dd = 0; dd < 4; dd++) {
            float xd = (&xv.x)[dd];
            ull xb = pack2(xd, xd);
            const ulonglong2* wr = reinterpret_cast<const ulonglong2*>(&Ws[(d4 * 4 + dd) * HID]);
            #pragma unroll
            for (int p = 0; p < 4; p++) {
                ulonglong2 w = wr[p];
                acc2[p * 2 + 0] = fma2(xb, w.x, acc2[p * 2 + 0]);
                acc2[p * 2 + 1] = fma2(xb, w.y, acc2[p * 2 + 1]);
            }
        }
    }
    ull* yr = reinterpret_cast<ull*>(y + (size_t)n * HID);
    #pragma unroll
    for (int j = 0; j < 8; j++) yr[j] = acc2[j];
}

// ---------------- 16-wide SpMM (v3 core): warp per row pair -----------------
// lanes = q(0..7 float2) x sub(0..3); 32 edges in flight per iteration.
// STATS: strided grid; fuses BN sufficient statistics (sum, A^T A) using the
// reduced rows already in registers (every lane holds q=lane&7 slice).
template<bool RELU, bool STATS>
__global__ void spmm16(const float* __restrict__ h, const float* __restrict__ vals,
                       const int* __restrict__ col, const float* __restrict__ bias,
                       float* __restrict__ out, double* __restrict__ gM,
                       double* __restrict__ gSum) {
    __shared__ float sM[HID * HID];
    __shared__ float sSum[HID];
    int t = threadIdx.x;
    if (STATS) {
        if (t < HID * HID) sM[t] = 0.f;
        if (t < HID) sSum[t] = 0.f;
        __syncthreads();
    }
    int lane = t & 31;
    int warp = t >> 5;
    int q = lane & 7;
    int sub = lane >> 3;
    const ull* h8 = reinterpret_cast<const ull*>(h);
    float b0 = 0.f, b1 = 0.f;
    if (RELU) { b0 = bias[2 * q]; b1 = bias[2 * q + 1]; }

    ull mAcc[4];      // 8 fp32 M-entries: row j=lane>>1, cols (lane&1)*8 + 0..7
    ull sumAcc = 0ull;
    #pragma unroll
    for (int s = 0; s < 4; s++) mAcc[s] = 0ull;

    int p0 = STATS ? (blockIdx.x * 8 + warp) : (blockIdx.x * 8 + warp);
    int pstep = STATS ? (STATS_BLK * 8) : (SPMM_BLK * 8 + 1);   // non-stats: single trip
    for (int p = p0; p < N_PAIRS; p += pstep) {
        int r0 = p * 2;
        int a0 = g_row_ptr[r0];
        int a1 = g_row_ptr[r0 + 1];
        int a2 = g_row_ptr[r0 + 2];
        int len = a2 - a0;
        ull accA = 0ull, accB = 0ull;
        for (int off = sub * 8; off < len; off += 32) {
            #pragma unroll
            for (int i = 0; i < 8; i++) {
                int o = off + i;
                bool valid = (o < len);
                int idx = valid ? (a0 + o) : (a2 - 1);
                float v = vals[idx];
                if (!valid) v = 0.f;
                int c = col[idx];
                ull hv = h8[(size_t)c * 8 + q];
                float vA = ((a0 + o) < a1) ? v : 0.f;
                float vB = v - vA;
                accA = fma2(pack2(vA, vA), hv, accA);
                accB = fma2(pack2(vB, vB), hv, accB);
            }
        }
        accA = add2(accA, __shfl_xor_sync(0xffffffffu, accA, 8));
        accA = add2(accA, __shfl_xor_sync(0xffffffffu, accA, 16));
        accB = add2(accB, __shfl_xor_sync(0xffffffffu, accB, 8));
        accB = add2(accB, __shfl_xor_sync(0xffffffffu, accB, 16));
        // now EVERY lane holds the final float2 for its q (duplicated over sub)
        if (sub == 0) {
            float x0, x1, y0, y1;
            unpack2(accA, x0, x1);
            unpack2(accB, y0, y1);
            if (RELU) {
                x0 = fmaxf(x0 + b0, 0.f); x1 = fmaxf(x1 + b1, 0.f);
                y0 = fmaxf(y0 + b0, 0.f); y1 = fmaxf(y1 + b1, 0.f);
            }
            float2* o2 = reinterpret_cast<float2*>(out);
            o2[(size_t)r0 * 8 + q]       = make_float2(x0, x1);
            o2[(size_t)(r0 + 1) * 8 + q] = make_float2(y0, y1);
        }
        if (STATS) {
            sumAcc = add2(sumAcc, add2(accA, accB));
            // outer product: lane owns M[j][k0..k0+7], j=lane>>1, k0=(lane&1)*8
            int srcj = lane >> 2;               // lane holding float2 containing a[j]
            int klane = (lane & 1) * 4;         // lanes holding the 4 k-float2s
            ull ja2 = shfl2(accA, srcj);
            ull jb2 = shfl2(accB, srcj);
            float jlA, jhA, jlB, jhB;
            unpack2(ja2, jlA, jhA);
            unpack2(jb2, jlB, jhB);
            float ajA = (lane & 2) ? jhA : jlA;
            float ajB = (lane & 2) ? jhB : jlB;
            ull ajA2 = pack2(ajA, ajA);
            ull ajB2 = pack2(ajB, ajB);
            #pragma unroll
            for (int s = 0; s < 4; s++) {
                ull kA = shfl2(accA, klane + s);
                ull kB = shfl2(accB, klane + s);
                mAcc[s] = fma2(ajA2, kA, mAcc[s]);
                mAcc[s] = fma2(ajB2, kB, mAcc[s]);
            }
        }
    }
    if (STATS) {
        int j = lane >> 1;
        int k0 = (lane & 1) * 8;
        #pragma unroll
        for (int s = 0; s < 4; s++) {
            float lo, hi;
            unpack2(mAcc[s], lo, hi);
            atomicAdd(&sM[j * HID + k0 + 2 * s],     lo);
            atomicAdd(&sM[j * HID + k0 + 2 * s + 1], hi);
        }
        if (sub == 0) {
            float lo, hi;
            unpack2(sumAcc, lo, hi);
            atomicAdd(&sSum[2 * q],     lo);
            atomicAdd(&sSum[2 * q + 1], hi);
        }
        __syncthreads();
        if (t < HID * HID) atomicAdd(&gM[t], (double)sM[t]);
        if (t < HID) atomicAdd(&gSum[t], (double)sSum[t]);
    }
}

// ---------------- fused: BN affine (per-block) + relu(bn(agg@W2)) @ W1next --
__global__ void fused_bn_gemm(const float* __restrict__ agg, const float* __restrict__ W2,
                              const float* __restrict__ W1n,
                              const double* __restrict__ gM,
                              const double* __restrict__ gSum,
                              const float* __restrict__ gamma,
                              const float* __restrict__ beta,
                              float* __restrict__ y) {
    __shared__ __align__(16) float W2s[HID * DIM];
    __shared__ __align__(16) float W1s[DIM * HID];
    __shared__ __align__(16) float scl[DIM];
    __shared__ __align__(16) float sft[DIM];
    __shared__ float  Mc[HID * HID];
    __shared__ double Ss[HID];
    int t = threadIdx.x;
    // --- BN affine prologue (redundant per block; cheap) ---
    if (t < HID) Ss[t] = gSum[t];
    for (int i = t; i < HID * DIM; i += TB) {
        W2s[i] = W2[i];
        W1s[i] = W1n[i];
    }
    __syncthreads();
    const double invN = 1.0 / (double)N_NODES;
    {
        int j = t >> 4, k = t & 15;
        Mc[t] = (float)(gM[t] - Ss[j] * Ss[k] * invN);
    }
    __syncthreads();
    if (t < DIM) {
        float wf[HID];
        #pragma unroll
        for (int kk = 0; kk < HID; kk++) wf[kk] = W2s[kk * DIM + t];
        double sn = 0.0;
        #pragma unroll
        for (int kk = 0; kk < HID; kk++) sn += Ss[kk] * (double)wf[kk];
        sn *= invN;
        float q0 = 0.f, q1 = 0.f, q2 = 0.f, q3 = 0.f;
        #pragma unroll
        for (int a = 0; a < HID; a++) {
            float wa = wf[a];
            #pragma unroll
            for (int b = 0; b < HID; b += 4) {
                q0 += Mc[a * HID + b + 0] * (wa * wf[b + 0]);
                q1 += Mc[a * HID + b + 1] * (wa * wf[b + 1]);
                q2 += Mc[a * HID + b + 2] * (wa * wf[b + 2]);
                q3 += Mc[a * HID + b + 3] * (wa * wf[b + 3]);
            }
        }
        float var = ((q0 + q1) + (q2 + q3)) * (float)invN;
        float scale = rsqrtf(fmaxf(var, 0.f) + BN_EPS) * gamma[t];
        scl[t] = scale;
        sft[t] = beta[t] - (float)sn * scale;   // b2 cancels in (h2-mean)
    }
    __syncthreads();
    int n = blockIdx.x * TB + t;
    if (n >= N_NODES) return;
    ull a2[HID];
    {
        const float4* ar = reinterpret_cast<const float4*>(agg + (size_t)n * HID);
        #pragma unroll
        for (int k4 = 0; k4 < 4; k4++) {
            float4 v = ar[k4];
            a2[k4*4+0] = pack2(v.x, v.x);
            a2[k4*4+1] = pack2(v.y, v.y);
            a2[k4*4+2] = pack2(v.z, v.z);
            a2[k4*4+3] = pack2(v.w, v.w);
        }
    }
    ull acc2[8];
    #pragma unroll
    for (int j = 0; j < 8; j++) acc2[j] = 0ull;
    #pragma unroll 2
    for (int cb = 0; cb < DIM; cb += 4) {
        ull t01 = 0ull, t23 = 0ull;
        const ulonglong2* w2p = reinterpret_cast<const ulonglong2*>(&W2s[cb]);
        #pragma unroll
        for (int k = 0; k < HID; k++) {
            ulonglong2 w = w2p[k * (DIM / 4)];
            t01 = fma2(a2[k], w.x, t01);
            t23 = fma2(a2[k], w.y, t23);
        }
        ulonglong2 sc = *reinterpret_cast<const ulonglong2*>(&scl[cb]);
        ulonglong2 sf = *reinterpret_cast<const ulonglong2*>(&sft[cb]);
        t01 = fma2(t01, sc.x, sf.x);
        t23 = fma2(t23, sc.y, sf.y);
        float v0, v1, v2, v3;
        unpack2(t01, v0, v1);
        unpack2(t23, v2, v3);
        v0 = fmaxf(v0, 0.f); v1 = fmaxf(v1, 0.f);
        v2 = fmaxf(v2, 0.f); v3 = fmaxf(v3, 0.f);
        ull vb[4] = { pack2(v0, v0), pack2(v1, v1), pack2(v2, v2), pack2(v3, v3) };
        #pragma unroll
        for (int c = 0; c < 4; c++) {
            const ulonglong2* w1p = reinterpret_cast<const ulonglong2*>(&W1s[(cb + c) * HID]);
            #pragma unroll
            for (int p = 0; p < 4; p++) {
                ulonglong2 w = w1p[p];
                acc2[p * 2 + 0] = fma2(vb[c], w.x, acc2[p * 2 + 0]);
                acc2[p * 2 + 1] = fma2(vb[c], w.y, acc2[p * 2 + 1]);
            }
        }
    }
    ull* yr = reinterpret_cast<ull*>(y + (size_t)n * HID);
    #pragma unroll
    for (int j = 0; j < 8; j++) yr[j] = acc2[j];
}

// ---------------- out[N,40] = agg[N,16] @ W[16,40] + b  (f32x2 packed) ------
__global__ void out_gemm(const float* __restrict__ agg, const float* __restrict__ W,
                         const float* __restrict__ b, float* __restrict__ out) {
    __shared__ __align__(16) float Ws[HID * NCLS];
    __shared__ __align__(16) float bs[NCLS];
    for (int i = threadIdx.x; i < HID * NCLS; i += TB) Ws[i] = W[i];
    if (threadIdx.x < NCLS) bs[threadIdx.x] = b[threadIdx.x];
    __syncthreads();
    int n = blockIdx.x * TB + threadIdx.x;
    if (n >= N_NODES) return;
    ull a2[HID];
    {
        const float4* ar = reinterpret_cast<const float4*>(agg + (size_t)n * HID);
        #pragma unroll
        for (int k4 = 0; k4 < 4; k4++) {
            float4 v = ar[k4];
            a2[k4*4+0] = pack2(v.x, v.x);
            a2[k4*4+1] = pack2(v.y, v.y);
            a2[k4*4+2] = pack2(v.z, v.z);
            a2[k4*4+3] = pack2(v.w, v.w);
        }
    }
    ull o2[NCLS / 2];
    const ull* bp = reinterpret_cast<const ull*>(bs);
    #pragma unroll
    for (int p = 0; p < NCLS / 2; p++) o2[p] = bp[p];
    #pragma unroll
    for (int k = 0; k < HID; k++) {
        const ull* wr = reinterpret_cast<const ull*>(&Ws[k * NCLS]);
        #pragma unroll
        for (int p = 0; p < NCLS / 2; p++)
            o2[p] = fma2(a2[k], wr[p], o2[p]);
    }
    ull* orow = reinterpret_cast<ull*>(out + (size_t)n * NCLS);
    #pragma unroll
    for (int p = 0; p < NCLS / 2; p++) orow[p] = o2[p];
}

// ============================================================================
extern "C" void kernel_launch(void* const* d_in, const int* in_sizes, int n_in,
                              void* d_out, int out_size) {
    const float* x     = (const float*)d_in[0];
    const float* vals  = (const float*)d_in[1];
    const float* W1    = (const float*)d_in[2];   // (3,128,16)
    const float* b1    = (const float*)d_in[3];   // (3,16)
    const float* W2    = (const float*)d_in[4];   // (3,16,128)
    const float* gamma = (const float*)d_in[6];   // (3,128)
    const float* beta  = (const float*)d_in[7];   // (3,128)
    const float* W1f   = (const float*)d_in[8];   // (128,16)
    const float* b1f   = (const float*)d_in[9];   // (16,)
    const float* W2f   = (const float*)d_in[10];  // (16,40)
    const float* b2f   = (const float*)d_in[11];  // (40,)
    const int*   row   = (const int*)d_in[12];
    const int*   col   = (const int*)d_in[13];
    float* out = (float*)d_out;
    // d_in[5] (b2) cancels inside batchnorm.

    float *p_h1, *p_s1, *p_agg;
    double *p_M3, *p_sum3;
    cudaGetSymbolAddress((void**)&p_h1,  g_h1);
    cudaGetSymbolAddress((void**)&p_s1,  g_s1);
    cudaGetSymbolAddress((void**)&p_agg, g_agg);
    cudaGetSymbolAddress((void**)&p_M3,  g_M3);
    cudaGetSymbolAddress((void**)&p_sum3, g_sum3);

    prolog_kernel<<<NODE_BLK + RP_BLK, TB>>>(row, x, W1, p_h1);

    for (int i = 0; i < 3; i++) {
        double* gM = p_M3 + (size_t)i * HID * HID;
        double* gS = p_sum3 + (size_t)i * HID;
        spmm16<true, false><<<SPMM_BLK, TB>>>(p_h1, vals, col, b1 + i * HID,
                                              p_s1, nullptr, nullptr);
        spmm16<false, true><<<STATS_BLK, TB>>>(p_s1, vals, col, nullptr,
                                               p_agg, gM, gS);
        const float* Wnext = (i < 2) ? (W1 + (size_t)(i + 1) * DIM * HID) : W1f;
        fused_bn_gemm<<<NODE_BLK, TB>>>(p_agg, W2 + (size_t)i * HID * DIM, Wnext,
                                        gM, gS, gamma + i * DIM, beta + i * DIM, p_h1);
    }

    spmm16<true, false><<<SPMM_BLK, TB>>>(p_h1, vals, col, b1f, p_s1, nullptr, nullptr);
    spmm16<false, false><<<SPMM_BLK, TB>>>(p_s1, vals, col, nullptr, p_agg, nullptr, nullptr);
    out_gemm<<<NODE_BLK, TB>>>(p_agg, W2f, b2f, out);
}